// round 16
// baseline (speedup 1.0000x reference)
#include <cuda_runtime.h>

// SSIM loss, (32,1,512,512) fp32. Single fused kernel, vertical-first FIR.
// R14: phase 1 = COLUMN-PAIR ring FIR. Even-aligned LDG.64 register pairs ARE
//      f32x2 operands (no packs); x/y/product channels all packed -> 33 FMA2
//      per 2 columns/output vs 44 mixed slots; LDG instructions -37%.
//      140 half-ring pair-items (16 out, 26 reads) over 128 threads.
//      Ring = 33 u64 accumulators -> launch_bounds(128,3) (no spills).
//      Phase 2 unchanged from R11 (window shifted +1: staging 1 col left).

#define IMG    512
#define TW     128
#define TH     32
#define VC     140        // staged cols: colE .. colE+139, colE = col0-1 (even)
#define NPAIR  70
#define PIT    141        // f32 stride 13 mod 32 (bij.); u64 stride 26 -> 16 bank-pairs
#define NT     128
#define SEGO   16         // outputs per phase-1 item
#define SEGR   26         // rows read per item
#define GX     4
#define GY     16
#define GZ     32
#define NBLK   (GX * GY * GZ)   // 2048

__device__ float        g_partials[NBLK];
__device__ unsigned int g_count;     // zero-init; self-resets

// normalized 1D Gaussian, K=11, sigma=1.5
#define W0 0.00102838f
#define W1 0.00759876f
#define W2 0.03600077f
#define W3 0.10936060f
#define W4 0.21300553f
#define W5 0.26601172f

#define FMA2(d, a, b, c) \
    asm("fma.rn.f32x2 %0, %1, %2, %3;" : "=l"(d) : "l"(a), "l"(b), "l"(c))
#define MUL2(d, a, b) \
    asm("mul.rn.f32x2 %0, %1, %2;" : "=l"(d) : "l"(a), "l"(b))
#define UNPK(lo, hi, v) \
    asm("mov.b64 {%0, %1}, %2;" : "=f"(lo), "=f"(hi) : "l"(v))
#define PK(v, lo, hi) \
    asm("mov.b64 %0, {%1, %2};" : "=l"(v) : "f"(lo), "f"(hi))

__device__ __forceinline__ unsigned long long pk2(float w) {
    unsigned long long r;
    asm("mov.b64 %0, {%1, %1};" : "=l"(r) : "f"(w));
    return r;
}

__global__ __launch_bounds__(NT, 3)
void ssim_fused_kernel(const float* __restrict__ X, const float* __restrict__ Y,
                       float* __restrict__ out)
{
    __shared__ unsigned long long vxy[TH][PIT];  // packed v-conv (x,y) 36.1KB
    __shared__ float              vp [TH][PIT];  // v-conv of x*y       18.0KB
    __shared__ float              wsum[4];
    __shared__ int                s_last;

    const float WGs[11] = {W0, W1, W2, W3, W4, W5, W4, W3, W2, W1, W0};
    const unsigned long long p0 = pk2(W0), p1 = pk2(W1), p2 = pk2(W2),
                             p3 = pk2(W3), p4 = pk2(W4), p5 = pk2(W5);
    const unsigned long long WP[11] = {p0,p1,p2,p3,p4,p5,p4,p3,p2,p1,p0};

    const int tid  = threadIdx.x;
    const int img  = blockIdx.z;
    const int row0 = blockIdx.y * TH - 5;
    const int col0 = blockIdx.x * TW - 5;
    const int colE = col0 - 1;                 // even

    const float* __restrict__ Xi = X + (size_t)img * IMG * IMG;
    const float* __restrict__ Yi = Y + (size_t)img * IMG * IMG;

    const bool rowsafe = (row0 >= 0) && (row0 + TH + 9 < IMG);

    // ---- phase 1: column-pair half-ring FIR: 140 items (128 + 12) ----
    // item = (pair u of 70, segment seg of 2); 16 outputs x 2 cols, 26 LDG.64 rows.
    #pragma unroll 1
    for (int i = tid; i < NPAIR * 2; i += NT) {
        const int u   = (i < NPAIR) ? i : (i - NPAIR);
        const int seg = (i < NPAIR) ? 0 : 1;
        const int gc  = colE + 2 * u;          // even, never straddles the edge
        const int rb  = row0 + seg * SEGO;
        const int ob  = seg * SEGO;
        const int s0  = 2 * u;

        if ((unsigned)gc < (unsigned)IMG) {
            const float2* __restrict__ px = (const float2*)(Xi + gc);
            const float2* __restrict__ py = (const float2*)(Yi + gc);

            unsigned long long axp[11], ayp[11], app[11];

            #pragma unroll
            for (int m = 0; m < SEGR; m++) {
                const int gr = rb + m;
                unsigned long long xv = 0ull, yv = 0ull;
                if (rowsafe || (unsigned)gr < (unsigned)IMG) {
                    float2 xf = __ldg(px + ((gr * IMG) >> 1));
                    float2 yf = __ldg(py + ((gr * IMG) >> 1));
                    xv = *(unsigned long long*)&xf;
                    yv = *(unsigned long long*)&yf;
                }
                unsigned long long pv;
                MUL2(pv, xv, yv);

                #pragma unroll
                for (int o = 0; o < SEGO; o++) {
                    if (o <= m && m <= o + 10) {
                        const int k = m - o;
                        const int s = o % 11;
                        if (k == 0) {            // first tap: init
                            MUL2(axp[s], xv, WP[0]);
                            MUL2(ayp[s], yv, WP[0]);
                            MUL2(app[s], pv, WP[0]);
                        } else {
                            FMA2(axp[s], xv, WP[k], axp[s]);
                            FMA2(ayp[s], yv, WP[k], ayp[s]);
                            FMA2(app[s], pv, WP[k], app[s]);
                        }
                    }
                }
                if (m >= 10) {                   // retire output o = m-10
                    const int o = m - 10;
                    const int s = o % 11;
                    float x0, x1, y0, y1, q0, q1;
                    UNPK(x0, x1, axp[s]);
                    UNPK(y0, y1, ayp[s]);
                    UNPK(q0, q1, app[s]);
                    unsigned long long v0, v1;
                    PK(v0, x0, y0);
                    PK(v1, x1, y1);
                    vxy[ob + o][s0]     = v0;
                    vxy[ob + o][s0 + 1] = v1;
                    vp [ob + o][s0]     = q0;
                    vp [ob + o][s0 + 1] = q1;
                }
            }
        } else {
            #pragma unroll
            for (int o = 0; o < SEGO; o++) {
                vxy[ob + o][s0]     = 0ull;
                vxy[ob + o][s0 + 1] = 0ull;
                vp [ob + o][s0]     = 0.0f;
                vp [ob + o][s0 + 1] = 0.0f;
            }
        }
    }
    __syncthreads();

    // ---- phase 2: horizontal FIR from smem + SSIM: 512 items, 4 rounds ----
    // staged col s = global - colE = tile col + 1 -> window starts at c0+1.
    const float C1 = 0.0001f, C2 = 0.0009f;
    float lsum = 0.0f;
    #pragma unroll 1
    for (int i = tid; i < TH * (TW / 8); i += NT) {
        const int r  = i & 31;
        const int c0 = (i >> 5) * 8 + 1;

        unsigned long long acc2[8];
        float accp[8];
        #pragma unroll
        for (int j = 0; j < 8; j++) { acc2[j] = 0ull; accp[j] = 0.0f; }

        #pragma unroll
        for (int m = 0; m < 18; m++) {
            unsigned long long v = vxy[r][c0 + m];   // LDS.64 feeds FMA2 directly
            float pm = vp[r][c0 + m];
            #pragma unroll
            for (int j = 0; j < 8; j++) {
                const int k = m - j;
                if (k >= 0 && k <= 10) {
                    FMA2(acc2[j], v, WP[k], acc2[j]);
                    accp[j] = fmaf(WGs[k], pm, accp[j]);
                }
            }
        }
        #pragma unroll
        for (int j = 0; j < 8; j++) {
            float mu1, mu2;
            UNPK(mu1, mu2, acc2[j]);
            float m12 = mu1 * mu2;
            float sig = accp[j] - m12;
            float sq  = mu1 * mu1 + mu2 * mu2;
            float num = (2.0f * m12 + C1) * (2.0f * sig + C2);
            float den = (sq + C1) * (sq + C2);
            lsum += __fdividef(num, den);
        }
    }

    // ---------------- block reduction (128 threads, 4 warps) ----------------
    #pragma unroll
    for (int off = 16; off > 0; off >>= 1)
        lsum += __shfl_xor_sync(0xFFFFFFFFu, lsum, off);
    if ((tid & 31) == 0) wsum[tid >> 5] = lsum;
    __syncthreads();
    if (tid == 0) {
        float v = wsum[0] + wsum[1] + wsum[2] + wsum[3];
        int bid = blockIdx.x + GX * (blockIdx.y + GY * blockIdx.z);
        g_partials[bid] = v;
        __threadfence();
        unsigned int ticket = atomicAdd(&g_count, 1u);
        s_last = (ticket == NBLK - 1);
    }
    __syncthreads();

    // ---------------- last block: final reduction ----------------
    if (s_last) {
        float s = 0.0f;
        #pragma unroll 4
        for (int i = tid; i < NBLK; i += NT)
            s += *((volatile float*)&g_partials[i]);
        #pragma unroll
        for (int off = 16; off > 0; off >>= 1)
            s += __shfl_xor_sync(0xFFFFFFFFu, s, off);
        __syncthreads();
        if ((tid & 31) == 0) wsum[tid >> 5] = s;
        __syncthreads();
        if (tid == 0) {
            out[0]  = (wsum[0] + wsum[1] + wsum[2] + wsum[3]) * (1.0f / 8388608.0f);
            g_count = 0;
        }
    }
}

extern "C" void kernel_launch(void* const* d_in, const int* in_sizes, int n_in,
                              void* d_out, int out_size)
{
    (void)in_sizes; (void)n_in; (void)out_size;
    const float* X_gt   = (const float*)d_in[0];
    const float* X_pred = (const float*)d_in[1];
    float* out = (float*)d_out;

    dim3 grid(GX, GY, GZ);
    ssim_fused_kernel<<<grid, NT>>>(X_gt, X_pred, out);
}

// round 17
// speedup vs baseline: 1.1142x; 1.1142x over previous
#include <cuda_runtime.h>

// SSIM loss, (32,1,512,512) fp32. Single fused kernel, vertical-first FIR.
// R15 = R11 + ring-FIR in phase 2: item = (row, 32-output segment), ring of
//       11 accumulators, 42 reads -> 32 outputs (1.31 loads/output vs 2.25),
//       SSIM inline at retire. 128 items / 128 threads = 1 balanced round.
// Kept from the session: 4 blocks/SM minimum (R14 falsified 3), scalar-column
// phase 1 (R9/R14 falsified pair-packing), no balance surgery (R12/R13 neutral).

#define IMG   512
#define TW    128
#define TH    32
#define VC    138         // staged cols (TW + 10)
#define PIT   139         // 139 mod 32 = 11 (f32), u64 stride 22 mod 32: conflict-free
#define NT    128
#define GX    4
#define GY    16
#define GZ    32
#define NBLK  (GX * GY * GZ)   // 2048

__device__ float        g_partials[NBLK];
__device__ unsigned int g_count;     // zero-init; self-resets

// normalized 1D Gaussian, K=11, sigma=1.5
#define W0 0.00102838f
#define W1 0.00759876f
#define W2 0.03600077f
#define W3 0.10936060f
#define W4 0.21300553f
#define W5 0.26601172f

#define FMA2(d, a, b, c) \
    asm("fma.rn.f32x2 %0, %1, %2, %3;" : "=l"(d) : "l"(a), "l"(b), "l"(c))
#define MUL2(d, a, b) \
    asm("mul.rn.f32x2 %0, %1, %2;" : "=l"(d) : "l"(a), "l"(b))
#define UNPK(lo, hi, v) \
    asm("mov.b64 {%0, %1}, %2;" : "=f"(lo), "=f"(hi) : "l"(v))
#define PK(v, lo, hi) \
    asm("mov.b64 %0, {%1, %2};" : "=l"(v) : "f"(lo), "f"(hi))

__device__ __forceinline__ unsigned long long pk2(float w) {
    unsigned long long r;
    asm("mov.b64 %0, {%1, %1};" : "=l"(r) : "f"(w));
    return r;
}

__global__ __launch_bounds__(NT, 4)
void ssim_fused_kernel(const float* __restrict__ X, const float* __restrict__ Y,
                       float* __restrict__ out)
{
    __shared__ unsigned long long vxy[TH][PIT];  // packed v-conv (x,y) 35.6KB
    __shared__ float              vp [TH][PIT];  // v-conv of x*y       17.8KB
    __shared__ float              wsum[4];
    __shared__ int                s_last;

    const float WGs[11] = {W0, W1, W2, W3, W4, W5, W4, W3, W2, W1, W0};
    const unsigned long long p0 = pk2(W0), p1 = pk2(W1), p2 = pk2(W2),
                             p3 = pk2(W3), p4 = pk2(W4), p5 = pk2(W5);
    const unsigned long long WP[11] = {p0,p1,p2,p3,p4,p5,p4,p3,p2,p1,p0};

    const int tid  = threadIdx.x;
    const int img  = blockIdx.z;
    const int row0 = blockIdx.y * TH - 5;
    const int col0 = blockIdx.x * TW - 5;

    const float* __restrict__ Xi = X + (size_t)img * IMG * IMG;
    const float* __restrict__ Yi = Y + (size_t)img * IMG * IMG;

    const bool rowsafe = (row0 >= 0) && (row0 + TH + 9 < IMG);

    // ---- phase 1: streaming vertical FIR, ring of 11 accumulators ----
    // item = column c (138 items); reads 42 rows, writes 32 outputs.
    #pragma unroll 1
    for (int c = tid; c < VC; c += NT) {
        const int gc = col0 + c;
        if ((unsigned)gc < (unsigned)IMG) {
            const float* __restrict__ px = Xi + gc;
            const float* __restrict__ py = Yi + gc;

            unsigned long long axy[11];
            float ap[11];

            #pragma unroll
            for (int m = 0; m < TH + 10; m++) {
                const int gr = row0 + m;
                const bool rok = rowsafe || ((unsigned)gr < (unsigned)IMG);
                float xv = rok ? __ldg(px + gr * IMG) : 0.0f;
                float yv = rok ? __ldg(py + gr * IMG) : 0.0f;
                unsigned long long v;
                PK(v, xv, yv);
                float pm = xv * yv;

                #pragma unroll
                for (int o = 0; o < TH; o++) {
                    if (o <= m && m <= o + 10) {
                        const int k = m - o;
                        if (k == 0) {             // first tap: init
                            MUL2(axy[o % 11], v, WP[0]);
                            ap[o % 11] = WGs[0] * pm;
                        } else {
                            FMA2(axy[o % 11], v, WP[k], axy[o % 11]);
                            ap[o % 11] = fmaf(WGs[k], pm, ap[o % 11]);
                        }
                    }
                }
                if (m >= 10) {                    // retire output o = m-10
                    const int o = m - 10;
                    vxy[o][c] = axy[o % 11];
                    vp [o][c] = ap [o % 11];
                }
            }
        } else {
            #pragma unroll
            for (int o = 0; o < TH; o++) { vxy[o][c] = 0ull; vp[o][c] = 0.0f; }
        }
    }
    __syncthreads();

    // ---- phase 2: horizontal ring FIR + inline SSIM: 128 items, 1 round ----
    // item = (row r of 32, segment s of 4): 42 reads -> 32 outputs.
    const float C1 = 0.0001f, C2 = 0.0009f;
    float lsum = 0.0f;
    {
        const int r  = tid & 31;
        const int cb = (tid >> 5) * 32;   // segment base (staged col == tile col)

        unsigned long long axy[11];
        float ap[11];

        #pragma unroll
        for (int m = 0; m < 42; m++) {
            unsigned long long v = vxy[r][cb + m];   // LDS.64 feeds FMA2 directly
            float pm = vp[r][cb + m];

            #pragma unroll
            for (int o = 0; o < 32; o++) {
                if (o <= m && m <= o + 10) {
                    const int k = m - o;
                    if (k == 0) {                 // first tap: init
                        MUL2(axy[o % 11], v, WP[0]);
                        ap[o % 11] = WGs[0] * pm;
                    } else {
                        FMA2(axy[o % 11], v, WP[k], axy[o % 11]);
                        ap[o % 11] = fmaf(WGs[k], pm, ap[o % 11]);
                    }
                }
            }
            if (m >= 10) {                        // retire output o = m-10: SSIM
                const int o = m - 10;
                float mu1, mu2;
                UNPK(mu1, mu2, axy[o % 11]);
                float m12 = mu1 * mu2;
                float sig = ap[o % 11] - m12;
                float sq  = mu1 * mu1 + mu2 * mu2;
                float num = (2.0f * m12 + C1) * (2.0f * sig + C2);
                float den = (sq + C1) * (sq + C2);
                lsum += __fdividef(num, den);
            }
        }
    }

    // ---------------- block reduction (128 threads, 4 warps) ----------------
    #pragma unroll
    for (int off = 16; off > 0; off >>= 1)
        lsum += __shfl_xor_sync(0xFFFFFFFFu, lsum, off);
    if ((tid & 31) == 0) wsum[tid >> 5] = lsum;
    __syncthreads();
    if (tid == 0) {
        float v = wsum[0] + wsum[1] + wsum[2] + wsum[3];
        int bid = blockIdx.x + GX * (blockIdx.y + GY * blockIdx.z);
        g_partials[bid] = v;
        __threadfence();
        unsigned int ticket = atomicAdd(&g_count, 1u);
        s_last = (ticket == NBLK - 1);
    }
    __syncthreads();

    // ---------------- last block: final reduction ----------------
    if (s_last) {
        float s = 0.0f;
        #pragma unroll 4
        for (int i = tid; i < NBLK; i += NT)
            s += *((volatile float*)&g_partials[i]);
        #pragma unroll
        for (int off = 16; off > 0; off >>= 1)
            s += __shfl_xor_sync(0xFFFFFFFFu, s, off);
        __syncthreads();
        if ((tid & 31) == 0) wsum[tid >> 5] = s;
        __syncthreads();
        if (tid == 0) {
            out[0]  = (wsum[0] + wsum[1] + wsum[2] + wsum[3]) * (1.0f / 8388608.0f);
            g_count = 0;
        }
    }
}

extern "C" void kernel_launch(void* const* d_in, const int* in_sizes, int n_in,
                              void* d_out, int out_size)
{
    (void)in_sizes; (void)n_in; (void)out_size;
    const float* X_gt   = (const float*)d_in[0];
    const float* X_pred = (const float*)d_in[1];
    float* out = (float*)d_out;

    dim3 grid(GX, GY, GZ);
    ssim_fused_kernel<<<grid, NT>>>(X_gt, X_pred, out);
}